// round 12
// baseline (speedup 1.0000x reference)
#include <cuda_runtime.h>
#include <cstdint>
#include <cstddef>

namespace {

constexpr int PAD_ID  = 72;     // VOCAB
constexpr int NB_MAIN = 592;    // 4 CTAs/SM * 148 SMs
constexpr int CTX_SEG = 512;    // tokens scanned per ctx block
constexpr int CTX_J   = 8;      // ctx tokens batched per Wt pass

// ctx_W transposed: g_Wt[k][d] = ctx_W[d][k]  (143 x 256 = 146 KB)
__device__ float g_Wt[143 * 256];

// warp LayerNorm stats over 256 values (8 per lane)
__device__ __forceinline__ void warp_ln(const float* h, float& mu, float& rs)
{
    float s1 = 0.f, s2 = 0.f;
#pragma unroll
    for (int k = 0; k < 8; ++k) { s1 += h[k]; s2 = fmaf(h[k], h[k], s2); }
#pragma unroll
    for (int o = 16; o; o >>= 1) {
        s1 += __shfl_xor_sync(0xffffffffu, s1, o);
        s2 += __shfl_xor_sync(0xffffffffu, s2, o);
    }
    mu = s1 * (1.f / 256.f);
    float var = s2 * (1.f / 256.f) - mu * mu;
    rs = rsqrtf(var + 1e-5f);
}

// ======================= main kernel (everything except ctx MLP) =======================
__global__ __launch_bounds__(256, 4) void poker_main_kernel(
    const int*   __restrict__ token_ids,
    const int*   __restrict__ token_streets,
    const int*   __restrict__ card_ranks,
    const int*   __restrict__ card_suits,
    const int*   __restrict__ action_actors,
    const float* __restrict__ legal_masks,   // [T,16]
    const float* __restrict__ cf,            // [T,9]
    const float* __restrict__ base_emb,      // [73,256]
    const float* __restrict__ street_emb,    // [4,256]
    const float* __restrict__ rank_emb,      // [13,256]
    const float* __restrict__ suit_emb,      // [4,256]
    const float* __restrict__ actor_emb,     // [2,256]
    const float* __restrict__ atype_emb,     // [16,256]
    const float* __restrict__ legal_W,       // [256,16]
    const float* __restrict__ legal_b,
    const float* __restrict__ legal_g,
    const float* __restrict__ legal_be,
    const float* __restrict__ game_W,        // [256,5]
    const float* __restrict__ game_b,
    const float* __restrict__ game_g,
    const float* __restrict__ game_be,
    const float* __restrict__ ctx_W,         // [256,143] (transposed here into g_Wt)
    float*       __restrict__ out,           // [T,256]
    int tokens)
{
    __shared__ float4 s_W[1024];        // swizzled legal_W (16 KB) — ONLY smem table

    const int tid  = threadIdx.x;
    const int lane = tid & 31;
    const int wid  = tid >> 5;

    // ---- fold the ctx_W transpose into the first 143 blocks (saves one launch) ----
    if (blockIdx.x < 143) {
        const int k = blockIdx.x;
        g_Wt[k * 256 + tid] = __ldg(ctx_W + tid * 143 + k);
    }

    {
        const float4* Wg = reinterpret_cast<const float4*>(legal_W);
        for (int q = tid; q < 1024; q += 256)
            s_W[q ^ ((q >> 5) & 7)] = Wg[q];
    }
    __syncthreads();   // the ONLY block barrier

    const int gwarp  = blockIdx.x * 8 + wid;
    const int nwarp  = gridDim.x * 8;
    const int l8     = lane << 3;
    const int swbase = (lane << 5);
    const int swxor  = lane & 7;
    const int lq     = lane * 2;

    // software pipeline: ids AND the base_emb gather are issued one iteration ahead
    int t   = gwarp;
    int raw = 0, st = 0;
    float4 b0 = make_float4(0.f,0.f,0.f,0.f), b1 = b0;
    if (t < tokens) {
        raw = __ldg(token_ids + t);
        st  = __ldg(token_streets + t);
        const int id0 = raw < 0 ? PAD_ID : raw;
        const float4* bp = reinterpret_cast<const float4*>(base_emb) + id0 * 64 + lq;
        b0 = __ldg(bp); b1 = __ldg(bp + 1);
    }

    while (t < tokens) {
        const int tn = t + nwarp;
        int raw_n = 0, st_n = 0;
        float4 b0n = make_float4(0.f,0.f,0.f,0.f), b1n = b0n;
        if (tn < tokens) {
            raw_n = __ldg(token_ids + tn);
            st_n  = __ldg(token_streets + tn);
            const int idn = raw_n < 0 ? PAD_ID : raw_n;
            const float4* bpn = reinterpret_cast<const float4*>(base_emb) + idn * 64 + lq;
            b0n = __ldg(bpn); b1n = __ldg(bpn + 1);
        }

        const bool pad = raw < 0;
        const int  id  = pad ? PAD_ID : raw;

        float ar[8];
        {
            const float4* sp = reinterpret_cast<const float4*>(street_emb) + st * 64 + lq;
            const float4 s0 = __ldg(sp), s1 = __ldg(sp + 1);
            ar[0] = b0.x + s0.x; ar[1] = b0.y + s0.y; ar[2] = b0.z + s0.z; ar[3] = b0.w + s0.w;
            ar[4] = b1.x + s1.x; ar[5] = b1.y + s1.y; ar[6] = b1.z + s1.z; ar[7] = b1.w + s1.w;
        }

        if (id >= 4 && id < 56) {
            // ---- card token ----
            int rk = __ldg(card_ranks + t); rk = rk < 0 ? 0 : (rk > 12 ? 12 : rk);
            int su = __ldg(card_suits + t); su = su < 0 ? 0 : (su > 3  ? 3  : su);
            const float4* rp = reinterpret_cast<const float4*>(rank_emb) + rk * 64 + lq;
            const float4* up = reinterpret_cast<const float4*>(suit_emb) + su * 64 + lq;
            const float4 r0 = __ldg(rp), r1 = __ldg(rp + 1);
            const float4 u0 = __ldg(up), u1 = __ldg(up + 1);
            ar[0] += r0.x + u0.x; ar[1] += r0.y + u0.y; ar[2] += r0.z + u0.z; ar[3] += r0.w + u0.w;
            ar[4] += r1.x + u1.x; ar[5] += r1.y + u1.y; ar[6] += r1.z + u1.z; ar[7] += r1.w + u1.w;
        } else if (id >= 56 && id < 72) {
            // ---- action token ----
            int ac = __ldg(action_actors + t); ac = ac < 0 ? 0 : (ac > 1 ? 1 : ac);
            const float4* ap = reinterpret_cast<const float4*>(actor_emb) + ac * 64 + lq;
            const float4* tp = reinterpret_cast<const float4*>(atype_emb) + (id - 56) * 64 + lq;
            const float4 a0 = __ldg(ap), a1 = __ldg(ap + 1);
            const float4 y0 = __ldg(tp), y1 = __ldg(tp + 1);
            ar[0] += a0.x + y0.x; ar[1] += a0.y + y0.y; ar[2] += a0.z + y0.z; ar[3] += a0.w + y0.w;
            ar[4] += a1.x + y1.x; ar[5] += a1.y + y1.y; ar[6] += a1.z + y1.z; ar[7] += a1.w + y1.w;

            const float4* xp = reinterpret_cast<const float4*>(legal_masks) + (size_t)t * 4;
            const float4 x0 = __ldg(xp), x1 = __ldg(xp + 1), x2 = __ldg(xp + 2), x3 = __ldg(xp + 3);

            float h[8];
            {
                const float4* bbp = reinterpret_cast<const float4*>(legal_b) + lq;
                const float4 hb0 = __ldg(bbp), hb1 = __ldg(bbp + 1);
                h[0]=hb0.x; h[1]=hb0.y; h[2]=hb0.z; h[3]=hb0.w;
                h[4]=hb1.x; h[5]=hb1.y; h[6]=hb1.z; h[7]=hb1.w;
            }
#pragma unroll
            for (int kk = 0; kk < 8; ++kk) {
                float4 w;
                w = s_W[swbase + (((kk << 2) | 0) ^ swxor)];
                h[kk] = fmaf(w.x, x0.x, h[kk]); h[kk] = fmaf(w.y, x0.y, h[kk]);
                h[kk] = fmaf(w.z, x0.z, h[kk]); h[kk] = fmaf(w.w, x0.w, h[kk]);
                w = s_W[swbase + (((kk << 2) | 1) ^ swxor)];
                h[kk] = fmaf(w.x, x1.x, h[kk]); h[kk] = fmaf(w.y, x1.y, h[kk]);
                h[kk] = fmaf(w.z, x1.z, h[kk]); h[kk] = fmaf(w.w, x1.w, h[kk]);
                w = s_W[swbase + (((kk << 2) | 2) ^ swxor)];
                h[kk] = fmaf(w.x, x2.x, h[kk]); h[kk] = fmaf(w.y, x2.y, h[kk]);
                h[kk] = fmaf(w.z, x2.z, h[kk]); h[kk] = fmaf(w.w, x2.w, h[kk]);
                w = s_W[swbase + (((kk << 2) | 3) ^ swxor)];
                h[kk] = fmaf(w.x, x3.x, h[kk]); h[kk] = fmaf(w.y, x3.y, h[kk]);
                h[kk] = fmaf(w.z, x3.z, h[kk]); h[kk] = fmaf(w.w, x3.w, h[kk]);
            }
            float mu, rs;
            warp_ln(h, mu, rs);
            const float4* gp = reinterpret_cast<const float4*>(legal_g)  + lq;
            const float4* ep = reinterpret_cast<const float4*>(legal_be) + lq;
            const float4 g0 = __ldg(gp), g1 = __ldg(gp + 1);
            const float4 e0 = __ldg(ep), e1 = __ldg(ep + 1);
            ar[0] += fmaxf(fmaf((h[0] - mu) * rs, g0.x, e0.x), 0.f);
            ar[1] += fmaxf(fmaf((h[1] - mu) * rs, g0.y, e0.y), 0.f);
            ar[2] += fmaxf(fmaf((h[2] - mu) * rs, g0.z, e0.z), 0.f);
            ar[3] += fmaxf(fmaf((h[3] - mu) * rs, g0.w, e0.w), 0.f);
            ar[4] += fmaxf(fmaf((h[4] - mu) * rs, g1.x, e1.x), 0.f);
            ar[5] += fmaxf(fmaf((h[5] - mu) * rs, g1.y, e1.y), 0.f);
            ar[6] += fmaxf(fmaf((h[6] - mu) * rs, g1.z, e1.z), 0.f);
            ar[7] += fmaxf(fmaf((h[7] - mu) * rs, g1.w, e1.w), 0.f);
        }

        // ---- game MLP: sequence position 0 only (256 occurrences total) ----
        if ((t & 511) == 0) {
            const int n = t >> 9;
            const float* c0 = cf + (size_t)n * 512 * 9;
            const float sb = __ldg(c0), bb = __ldg(c0 + 1), po = __ldg(c0 + 2);
            const float scale = 100.f * bb;
            const float ssg = (scale == 0.f) ? 1e-8f : scale;
            const float f3 = bb / ssg, f4 = sb / ssg;
            float h[8];
            {
                const float4* bbp = reinterpret_cast<const float4*>(game_b) + lq;
                const float4 hb0 = __ldg(bbp), hb1 = __ldg(bbp + 1);
                h[0]=hb0.x; h[1]=hb0.y; h[2]=hb0.z; h[3]=hb0.w;
                h[4]=hb1.x; h[5]=hb1.y; h[6]=hb1.z; h[7]=hb1.w;
            }
#pragma unroll
            for (int kk = 0; kk < 8; ++kk) {
                const float* wr = game_W + (size_t)(l8 + kk) * 5;
                float s = h[kk];
                s = fmaf(__ldg(wr + 0), sb, s);
                s = fmaf(__ldg(wr + 1), bb, s);
                s = fmaf(__ldg(wr + 2), po, s);
                s = fmaf(__ldg(wr + 3), f3, s);
                s = fmaf(__ldg(wr + 4), f4, s);
                h[kk] = s;
            }
            float mu, rs;
            warp_ln(h, mu, rs);
            const float4* gp = reinterpret_cast<const float4*>(game_g)  + lq;
            const float4* ep = reinterpret_cast<const float4*>(game_be) + lq;
            const float4 g0 = __ldg(gp), g1 = __ldg(gp + 1);
            const float4 e0 = __ldg(ep), e1 = __ldg(ep + 1);
            ar[0] += fmaxf(fmaf((h[0] - mu) * rs, g0.x, e0.x), 0.f);
            ar[1] += fmaxf(fmaf((h[1] - mu) * rs, g0.y, e0.y), 0.f);
            ar[2] += fmaxf(fmaf((h[2] - mu) * rs, g0.z, e0.z), 0.f);
            ar[3] += fmaxf(fmaf((h[3] - mu) * rs, g0.w, e0.w), 0.f);
            ar[4] += fmaxf(fmaf((h[4] - mu) * rs, g1.x, e1.x), 0.f);
            ar[5] += fmaxf(fmaf((h[5] - mu) * rs, g1.y, e1.y), 0.f);
            ar[6] += fmaxf(fmaf((h[6] - mu) * rs, g1.z, e1.z), 0.f);
            ar[7] += fmaxf(fmaf((h[7] - mu) * rs, g1.w, e1.w), 0.f);
        }

        // ---- store (pad -> 0), vectorized ----
        float4 o0, o1;
        if (pad) {
            o0 = make_float4(0.f, 0.f, 0.f, 0.f);
            o1 = o0;
        } else {
            o0 = make_float4(ar[0], ar[1], ar[2], ar[3]);
            o1 = make_float4(ar[4], ar[5], ar[6], ar[7]);
        }
        float4* op = reinterpret_cast<float4*>(out) + (size_t)t * 64 + lq;
        op[0] = o0;
        op[1] = o1;

        t = tn; raw = raw_n; st = st_n; b0 = b0n; b1 = b1n;
    }
}

// ============ ctx kernel: scan 512-token segment, batch 8 tokens per Wt pass ============
__global__ __launch_bounds__(256, 4) void poker_ctx_kernel(
    const int*   __restrict__ token_ids,
    const float* __restrict__ cf,            // [T,9]
    const float* __restrict__ ctx_b,
    const float* __restrict__ ctx_g,
    const float* __restrict__ ctx_be,
    float*       __restrict__ out,           // [T,256]
    int tokens)
{
    __shared__ float s_ca[CTX_J][144];
    __shared__ float s_red[8][CTX_J][2];
    __shared__ float s_ms[CTX_J][2];
    __shared__ int   s_list[CTX_SEG];
    __shared__ int   s_cnt;

    const int tid  = threadIdx.x;
    const int lane = tid & 31;
    const int wid  = tid >> 5;

    // ---- scan this block's 512-token segment for ctx tokens (id == 1) ----
    const int s0 = blockIdx.x * CTX_SEG;
    if (tid == 0) s_cnt = 0;
    __syncthreads();
#pragma unroll
    for (int q = tid; q < CTX_SEG; q += 256) {
        const int tt = s0 + q;
        if (tt < tokens && __ldg(token_ids + tt) == 1) {
            const int k = atomicAdd(&s_cnt, 1);
            s_list[k] = tt;
        }
    }
    __syncthreads();
    const int m = s_cnt;
    if (m == 0) return;

    const float hb = __ldg(ctx_b  + tid);
    const float gg = __ldg(ctx_g  + tid);
    const float ee = __ldg(ctx_be + tid);
    const float* wt = g_Wt + tid;

    for (int base = 0; base < m; base += CTX_J) {
        const int J = (m - base < CTX_J) ? (m - base) : CTX_J;

        // ---- warp w builds ca[143] for token base+w ----
        if (wid < J) {
            const int t = s_list[base + wid];
            const int n = t >> 9;
            const float* c0 = cf + (size_t)n * 512 * 9;
            const float* cp = cf + (size_t)t * 9;
            const float bb = __ldg(c0 + 1);
            const float scale = 100.f * bb;
            const float ssafe   = (scale == 0.f) ? 1.f : scale;
            const float bbsafe  = (bb == 0.f) ? 1.f : bb;
            const float pot     = __ldg(cp);
            const float potsafe = (pot == 0.f) ? 1.f : pot;
#pragma unroll
            for (int i = 0; i < 5; ++i) {
                const int idx = lane + 32 * i;
                if (idx < 143) {
                    const int fi = idx / 11;
                    const int ps = idx - fi * 11;
                    const int si = (fi < 9) ? fi : ((fi < 11) ? fi - 8 : fi - 10);
                    const float num = __ldg(cp + si);
                    float den = ssafe;
                    if (fi == 5 || fi == 6)       den = 1.f;
                    else if (fi == 9 || fi == 10) den = bbsafe;
                    else if (fi >= 11)            den = potsafe;
                    const float pv = num / den;
                    float val;
                    if (ps == 0)      val = pv;
                    else if (ps <= 5) val = sinpif(pv * (float)(1 << (ps - 1)));
                    else              val = cospif(pv * (float)(1 << (ps - 6)));
                    s_ca[wid][idx] = val;
                } else if (idx < 144) {
                    s_ca[wid][idx] = 0.f;
                }
            }
        }
        __syncthreads();

        // ---- batched dot: one Wt load feeds CTX_J FMAs ----
        float h[CTX_J];
#pragma unroll
        for (int j = 0; j < CTX_J; ++j) h[j] = hb;
        int k = 0;
#pragma unroll 2
        for (; k + 4 <= 143; k += 4) {
            const float w0 = wt[(k + 0) * 256];
            const float w1 = wt[(k + 1) * 256];
            const float w2 = wt[(k + 2) * 256];
            const float w3 = wt[(k + 3) * 256];
#pragma unroll
            for (int j = 0; j < CTX_J; ++j) {
                h[j] = fmaf(s_ca[j][k + 0], w0, h[j]);
                h[j] = fmaf(s_ca[j][k + 1], w1, h[j]);
                h[j] = fmaf(s_ca[j][k + 2], w2, h[j]);
                h[j] = fmaf(s_ca[j][k + 3], w3, h[j]);
            }
        }
        for (; k < 143; ++k) {
            const float w0 = wt[k * 256];
#pragma unroll
            for (int j = 0; j < CTX_J; ++j) h[j] = fmaf(s_ca[j][k], w0, h[j]);
        }

        // ---- batched block LayerNorm over 256 dims, all J tokens ----
#pragma unroll
        for (int j = 0; j < CTX_J; ++j) {
            float a = h[j], b = h[j] * h[j];
#pragma unroll
            for (int o = 16; o; o >>= 1) {
                a += __shfl_xor_sync(0xffffffffu, a, o);
                b += __shfl_xor_sync(0xffffffffu, b, o);
            }
            if (lane == 0) { s_red[wid][j][0] = a; s_red[wid][j][1] = b; }
        }
        __syncthreads();
        if (tid < CTX_J) {
            float t1 = 0.f, t2 = 0.f;
#pragma unroll
            for (int w = 0; w < 8; ++w) { t1 += s_red[w][tid][0]; t2 += s_red[w][tid][1]; }
            const float mu  = t1 * (1.f / 256.f);
            const float var = t2 * (1.f / 256.f) - mu * mu;
            s_ms[tid][0] = mu;
            s_ms[tid][1] = rsqrtf(var + 1e-5f);
        }
        __syncthreads();

        // ---- epilogue: relu(LN) added to out, one token at a time (coalesced) ----
        for (int j = 0; j < J; ++j) {
            const int t = s_list[base + j];
            const float v = fmaf((h[j] - s_ms[j][0]) * s_ms[j][1], gg, ee);
            out[(size_t)t * 256 + tid] += fmaxf(v, 0.f);
        }
        __syncthreads();   // s_ca/s_red reuse guard for next pass
    }
}

} // namespace

extern "C" void kernel_launch(void* const* d_in, const int* in_sizes, int n_in,
                              void* d_out, int out_size)
{
    const int tokens = in_sizes[0];   // N*S

    poker_main_kernel<<<NB_MAIN, 256>>>(
        (const int*)  d_in[0],   // token_ids
        (const int*)  d_in[1],   // token_streets
        (const int*)  d_in[2],   // card_ranks
        (const int*)  d_in[3],   // card_suits
        (const int*)  d_in[4],   // action_actors
        (const float*)d_in[5],   // action_legal_masks
        (const float*)d_in[6],   // context_features
        (const float*)d_in[7],   // base_emb
        (const float*)d_in[8],   // street_emb
        (const float*)d_in[9],   // rank_emb
        (const float*)d_in[10],  // suit_emb
        (const float*)d_in[11],  // actor_emb
        (const float*)d_in[12],  // atype_emb
        (const float*)d_in[13],  // legal_W
        (const float*)d_in[14],  // legal_b
        (const float*)d_in[15],  // legal_g
        (const float*)d_in[16],  // legal_beta
        (const float*)d_in[17],  // game_W
        (const float*)d_in[18],  // game_b
        (const float*)d_in[19],  // game_g
        (const float*)d_in[20],  // game_beta
        (const float*)d_in[21],  // ctx_W (transposed in-kernel)
        (float*)d_out,
        tokens);

    const int nb_ctx = (tokens + CTX_SEG - 1) / CTX_SEG;
    poker_ctx_kernel<<<nb_ctx, 256>>>(
        (const int*)  d_in[0],   // token_ids
        (const float*)d_in[6],   // context_features
        (const float*)d_in[22],  // ctx_b
        (const float*)d_in[23],  // ctx_g
        (const float*)d_in[24],  // ctx_beta
        (float*)d_out,
        tokens);
}

// round 13
// speedup vs baseline: 1.1429x; 1.1429x over previous
#include <cuda_runtime.h>
#include <cstdint>
#include <cstddef>

namespace {

constexpr int PAD_ID  = 72;     // VOCAB
constexpr int NB_MAIN = 592;    // 4 CTAs/SM * 148 SMs — exactly one wave
constexpr int CTX_J   = 4;      // ctx tokens batched per Wt pass
constexpr int CLIST   = 232;    // >= max tokens one CTA can own (8 warps * 28)

// ctx_W transposed: g_Wt[k][d] = ctx_W[d][k]  (143 x 256 = 146 KB)
__device__ float g_Wt[143 * 256];

// warp LayerNorm stats over 256 values (8 per lane)
__device__ __forceinline__ void warp_ln(const float* h, float& mu, float& rs)
{
    float s1 = 0.f, s2 = 0.f;
#pragma unroll
    for (int k = 0; k < 8; ++k) { s1 += h[k]; s2 = fmaf(h[k], h[k], s2); }
#pragma unroll
    for (int o = 16; o; o >>= 1) {
        s1 += __shfl_xor_sync(0xffffffffu, s1, o);
        s2 += __shfl_xor_sync(0xffffffffu, s2, o);
    }
    mu = s1 * (1.f / 256.f);
    float var = s2 * (1.f / 256.f) - mu * mu;
    rs = rsqrtf(var + 1e-5f);
}

// =================== single fused kernel: embeddings + MLPs + deferred ctx ===================
__global__ __launch_bounds__(256, 4) void poker_fused_kernel(
    const int*   __restrict__ token_ids,
    const int*   __restrict__ token_streets,
    const int*   __restrict__ card_ranks,
    const int*   __restrict__ card_suits,
    const int*   __restrict__ action_actors,
    const float* __restrict__ legal_masks,   // [T,16]
    const float* __restrict__ cf,            // [T,9]
    const float* __restrict__ base_emb,      // [73,256]
    const float* __restrict__ street_emb,    // [4,256]
    const float* __restrict__ rank_emb,      // [13,256]
    const float* __restrict__ suit_emb,      // [4,256]
    const float* __restrict__ actor_emb,     // [2,256]
    const float* __restrict__ atype_emb,     // [16,256]
    const float* __restrict__ legal_W,       // [256,16]
    const float* __restrict__ legal_b,
    const float* __restrict__ legal_g,
    const float* __restrict__ legal_be,
    const float* __restrict__ game_W,        // [256,5]
    const float* __restrict__ game_b,
    const float* __restrict__ game_g,
    const float* __restrict__ game_be,
    const float* __restrict__ ctx_W,         // [256,143] (transposed into g_Wt)
    const float* __restrict__ ctx_b,
    const float* __restrict__ ctx_g,
    const float* __restrict__ ctx_be,
    float*       __restrict__ out,           // [T,256]
    int tokens)
{
    __shared__ float4 s_W[1024];             // swizzled legal_W (16 KB)
    __shared__ int    s_clist[CLIST];
    __shared__ int    s_ccnt;
    __shared__ float  s_ca[CTX_J][144];
    __shared__ float  s_red[8][CTX_J][2];
    __shared__ float  s_ms[CTX_J][2];

    const int tid  = threadIdx.x;
    const int lane = tid & 31;
    const int wid  = tid >> 5;

    // ---- fold the ctx_W transpose into the first 143 blocks.
    // Safe: grid is exactly one co-resident wave (launch_bounds-guaranteed), these
    // writes finish within ~2k cycles, first g_Wt read is after each CTA's full loop.
    if (blockIdx.x < 143) {
        const int k = blockIdx.x;
        g_Wt[k * 256 + tid] = __ldg(ctx_W + tid * 143 + k);
    }

    if (tid == 0) s_ccnt = 0;
    {
        const float4* Wg = reinterpret_cast<const float4*>(legal_W);
        for (int q = tid; q < 1024; q += 256)
            s_W[q ^ ((q >> 5) & 7)] = Wg[q];
    }
    __syncthreads();

    const int gwarp  = blockIdx.x * 8 + wid;
    const int nwarp  = gridDim.x * 8;
    const int l8     = lane << 3;
    const int swbase = (lane << 5);
    const int swxor  = lane & 7;
    const int lq     = lane * 2;

    // software pipeline: ids AND the base_emb gather issued one iteration ahead
    int t   = gwarp;
    int raw = 0, st = 0;
    float4 b0 = make_float4(0.f,0.f,0.f,0.f), b1 = b0;
    if (t < tokens) {
        raw = __ldg(token_ids + t);
        st  = __ldg(token_streets + t);
        const int id0 = raw < 0 ? PAD_ID : raw;
        const float4* bp = reinterpret_cast<const float4*>(base_emb) + id0 * 64 + lq;
        b0 = __ldg(bp); b1 = __ldg(bp + 1);
    }

    while (t < tokens) {
        const int tn = t + nwarp;
        int raw_n = 0, st_n = 0;
        float4 b0n = make_float4(0.f,0.f,0.f,0.f), b1n = b0n;
        if (tn < tokens) {
            raw_n = __ldg(token_ids + tn);
            st_n  = __ldg(token_streets + tn);
            const int idn = raw_n < 0 ? PAD_ID : raw_n;
            const float4* bpn = reinterpret_cast<const float4*>(base_emb) + idn * 64 + lq;
            b0n = __ldg(bpn); b1n = __ldg(bpn + 1);
        }

        const bool pad = raw < 0;
        const int  id  = pad ? PAD_ID : raw;

        float ar[8];
        {
            const float4* sp = reinterpret_cast<const float4*>(street_emb) + st * 64 + lq;
            const float4 s0 = __ldg(sp), s1 = __ldg(sp + 1);
            ar[0] = b0.x + s0.x; ar[1] = b0.y + s0.y; ar[2] = b0.z + s0.z; ar[3] = b0.w + s0.w;
            ar[4] = b1.x + s1.x; ar[5] = b1.y + s1.y; ar[6] = b1.z + s1.z; ar[7] = b1.w + s1.w;
        }

        if (id >= 4 && id < 56) {
            // ---- card token ----
            int rk = __ldg(card_ranks + t); rk = rk < 0 ? 0 : (rk > 12 ? 12 : rk);
            int su = __ldg(card_suits + t); su = su < 0 ? 0 : (su > 3  ? 3  : su);
            const float4* rp = reinterpret_cast<const float4*>(rank_emb) + rk * 64 + lq;
            const float4* up = reinterpret_cast<const float4*>(suit_emb) + su * 64 + lq;
            const float4 r0 = __ldg(rp), r1 = __ldg(rp + 1);
            const float4 u0 = __ldg(up), u1 = __ldg(up + 1);
            ar[0] += r0.x + u0.x; ar[1] += r0.y + u0.y; ar[2] += r0.z + u0.z; ar[3] += r0.w + u0.w;
            ar[4] += r1.x + u1.x; ar[5] += r1.y + u1.y; ar[6] += r1.z + u1.z; ar[7] += r1.w + u1.w;
        } else if (id >= 56 && id < 72) {
            // ---- action token ----
            int ac = __ldg(action_actors + t); ac = ac < 0 ? 0 : (ac > 1 ? 1 : ac);
            const float4* ap = reinterpret_cast<const float4*>(actor_emb) + ac * 64 + lq;
            const float4* tp = reinterpret_cast<const float4*>(atype_emb) + (id - 56) * 64 + lq;
            const float4 a0 = __ldg(ap), a1 = __ldg(ap + 1);
            const float4 y0 = __ldg(tp), y1 = __ldg(tp + 1);
            ar[0] += a0.x + y0.x; ar[1] += a0.y + y0.y; ar[2] += a0.z + y0.z; ar[3] += a0.w + y0.w;
            ar[4] += a1.x + y1.x; ar[5] += a1.y + y1.y; ar[6] += a1.z + y1.z; ar[7] += a1.w + y1.w;

            const float4* xp = reinterpret_cast<const float4*>(legal_masks) + (size_t)t * 4;
            const float4 x0 = __ldg(xp), x1 = __ldg(xp + 1), x2 = __ldg(xp + 2), x3 = __ldg(xp + 3);

            float h[8];
            {
                const float4* bbp = reinterpret_cast<const float4*>(legal_b) + lq;
                const float4 hb0 = __ldg(bbp), hb1 = __ldg(bbp + 1);
                h[0]=hb0.x; h[1]=hb0.y; h[2]=hb0.z; h[3]=hb0.w;
                h[4]=hb1.x; h[5]=hb1.y; h[6]=hb1.z; h[7]=hb1.w;
            }
#pragma unroll
            for (int kk = 0; kk < 8; ++kk) {
                float4 w;
                w = s_W[swbase + (((kk << 2) | 0) ^ swxor)];
                h[kk] = fmaf(w.x, x0.x, h[kk]); h[kk] = fmaf(w.y, x0.y, h[kk]);
                h[kk] = fmaf(w.z, x0.z, h[kk]); h[kk] = fmaf(w.w, x0.w, h[kk]);
                w = s_W[swbase + (((kk << 2) | 1) ^ swxor)];
                h[kk] = fmaf(w.x, x1.x, h[kk]); h[kk] = fmaf(w.y, x1.y, h[kk]);
                h[kk] = fmaf(w.z, x1.z, h[kk]); h[kk] = fmaf(w.w, x1.w, h[kk]);
                w = s_W[swbase + (((kk << 2) | 2) ^ swxor)];
                h[kk] = fmaf(w.x, x2.x, h[kk]); h[kk] = fmaf(w.y, x2.y, h[kk]);
                h[kk] = fmaf(w.z, x2.z, h[kk]); h[kk] = fmaf(w.w, x2.w, h[kk]);
                w = s_W[swbase + (((kk << 2) | 3) ^ swxor)];
                h[kk] = fmaf(w.x, x3.x, h[kk]); h[kk] = fmaf(w.y, x3.y, h[kk]);
                h[kk] = fmaf(w.z, x3.z, h[kk]); h[kk] = fmaf(w.w, x3.w, h[kk]);
            }
            float mu, rs;
            warp_ln(h, mu, rs);
            const float4* gp = reinterpret_cast<const float4*>(legal_g)  + lq;
            const float4* ep = reinterpret_cast<const float4*>(legal_be) + lq;
            const float4 g0 = __ldg(gp), g1 = __ldg(gp + 1);
            const float4 e0 = __ldg(ep), e1 = __ldg(ep + 1);
            ar[0] += fmaxf(fmaf((h[0] - mu) * rs, g0.x, e0.x), 0.f);
            ar[1] += fmaxf(fmaf((h[1] - mu) * rs, g0.y, e0.y), 0.f);
            ar[2] += fmaxf(fmaf((h[2] - mu) * rs, g0.z, e0.z), 0.f);
            ar[3] += fmaxf(fmaf((h[3] - mu) * rs, g0.w, e0.w), 0.f);
            ar[4] += fmaxf(fmaf((h[4] - mu) * rs, g1.x, e1.x), 0.f);
            ar[5] += fmaxf(fmaf((h[5] - mu) * rs, g1.y, e1.y), 0.f);
            ar[6] += fmaxf(fmaf((h[6] - mu) * rs, g1.z, e1.z), 0.f);
            ar[7] += fmaxf(fmaf((h[7] - mu) * rs, g1.w, e1.w), 0.f);
        } else if (id == 1) {
            // ---- ctx token: defer to the CTA tail pass ----
            if (lane == 0) {
                const int k = atomicAdd(&s_ccnt, 1);
                s_clist[k] = t;
            }
        }

        // ---- game MLP: sequence position 0 only (256 occurrences total) ----
        if ((t & 511) == 0) {
            const int n = t >> 9;
            const float* c0 = cf + (size_t)n * 512 * 9;
            const float sb = __ldg(c0), bb = __ldg(c0 + 1), po = __ldg(c0 + 2);
            const float scale = 100.f * bb;
            const float ssg = (scale == 0.f) ? 1e-8f : scale;
            const float f3 = bb / ssg, f4 = sb / ssg;
            float h[8];
            {
                const float4* bbp = reinterpret_cast<const float4*>(game_b) + lq;
                const float4 hb0 = __ldg(bbp), hb1 = __ldg(bbp + 1);
                h[0]=hb0.x; h[1]=hb0.y; h[2]=hb0.z; h[3]=hb0.w;
                h[4]=hb1.x; h[5]=hb1.y; h[6]=hb1.z; h[7]=hb1.w;
            }
#pragma unroll
            for (int kk = 0; kk < 8; ++kk) {
                const float* wr = game_W + (size_t)(l8 + kk) * 5;
                float s = h[kk];
                s = fmaf(__ldg(wr + 0), sb, s);
                s = fmaf(__ldg(wr + 1), bb, s);
                s = fmaf(__ldg(wr + 2), po, s);
                s = fmaf(__ldg(wr + 3), f3, s);
                s = fmaf(__ldg(wr + 4), f4, s);
                h[kk] = s;
            }
            float mu, rs;
            warp_ln(h, mu, rs);
            const float4* gp = reinterpret_cast<const float4*>(game_g)  + lq;
            const float4* ep = reinterpret_cast<const float4*>(game_be) + lq;
            const float4 g0 = __ldg(gp), g1 = __ldg(gp + 1);
            const float4 e0 = __ldg(ep), e1 = __ldg(ep + 1);
            ar[0] += fmaxf(fmaf((h[0] - mu) * rs, g0.x, e0.x), 0.f);
            ar[1] += fmaxf(fmaf((h[1] - mu) * rs, g0.y, e0.y), 0.f);
            ar[2] += fmaxf(fmaf((h[2] - mu) * rs, g0.z, e0.z), 0.f);
            ar[3] += fmaxf(fmaf((h[3] - mu) * rs, g0.w, e0.w), 0.f);
            ar[4] += fmaxf(fmaf((h[4] - mu) * rs, g1.x, e1.x), 0.f);
            ar[5] += fmaxf(fmaf((h[5] - mu) * rs, g1.y, e1.y), 0.f);
            ar[6] += fmaxf(fmaf((h[6] - mu) * rs, g1.z, e1.z), 0.f);
            ar[7] += fmaxf(fmaf((h[7] - mu) * rs, g1.w, e1.w), 0.f);
        }

        // ---- store (pad -> 0), vectorized ----
        float4 o0, o1;
        if (pad) {
            o0 = make_float4(0.f, 0.f, 0.f, 0.f);
            o1 = o0;
        } else {
            o0 = make_float4(ar[0], ar[1], ar[2], ar[3]);
            o1 = make_float4(ar[4], ar[5], ar[6], ar[7]);
        }
        float4* op = reinterpret_cast<float4*>(out) + (size_t)t * 64 + lq;
        op[0] = o0;
        op[1] = o1;

        t = tn; raw = raw_n; st = st_n; b0 = b0n; b1 = b1n;
    }

    // =================== CTA tail: deferred ctx MLP, J-batched over one Wt stream ===================
    __syncthreads();                 // list complete + loop stores ordered before RMW
    const int m = s_ccnt;
    if (m == 0) return;

    const float hb = __ldg(ctx_b  + tid);
    const float cg = __ldg(ctx_g  + tid);
    const float ce = __ldg(ctx_be + tid);
    const float* wt = g_Wt + tid;

    for (int base = 0; base < m; base += CTX_J) {
        const int J = (m - base < CTX_J) ? (m - base) : CTX_J;

        // ---- warp w builds ca[143] for token base+w ----
        if (wid < J) {
            const int tt = s_clist[base + wid];
            const int n  = tt >> 9;
            const float* c0 = cf + (size_t)n * 512 * 9;
            const float* cp = cf + (size_t)tt * 9;
            const float bb = __ldg(c0 + 1);
            const float scale = 100.f * bb;
            const float ssafe   = (scale == 0.f) ? 1.f : scale;
            const float bbsafe  = (bb == 0.f) ? 1.f : bb;
            const float pot     = __ldg(cp);
            const float potsafe = (pot == 0.f) ? 1.f : pot;
#pragma unroll
            for (int i = 0; i < 5; ++i) {
                const int idx = lane + 32 * i;
                if (idx < 143) {
                    const int fi = idx / 11;
                    const int ps = idx - fi * 11;
                    const int si = (fi < 9) ? fi : ((fi < 11) ? fi - 8 : fi - 10);
                    const float num = __ldg(cp + si);
                    float den = ssafe;
                    if (fi == 5 || fi == 6)       den = 1.f;
                    else if (fi == 9 || fi == 10) den = bbsafe;
                    else if (fi >= 11)            den = potsafe;
                    const float pv = num / den;
                    float val;
                    if (ps == 0)      val = pv;
                    else if (ps <= 5) val = sinpif(pv * (float)(1 << (ps - 1)));
                    else              val = cospif(pv * (float)(1 << (ps - 6)));
                    s_ca[wid][idx] = val;
                } else if (idx < 144) {
                    s_ca[wid][idx] = 0.f;
                }
            }
        }
        __syncthreads();

        // ---- batched dot: one Wt load feeds CTX_J FMAs ----
        float h[CTX_J];
#pragma unroll
        for (int j = 0; j < CTX_J; ++j) h[j] = hb;
        int k = 0;
        for (; k + 4 <= 143; k += 4) {
            const float w0 = wt[(k + 0) * 256];
            const float w1 = wt[(k + 1) * 256];
            const float w2 = wt[(k + 2) * 256];
            const float w3 = wt[(k + 3) * 256];
#pragma unroll
            for (int j = 0; j < CTX_J; ++j) {
                h[j] = fmaf(s_ca[j][k + 0], w0, h[j]);
                h[j] = fmaf(s_ca[j][k + 1], w1, h[j]);
                h[j] = fmaf(s_ca[j][k + 2], w2, h[j]);
                h[j] = fmaf(s_ca[j][k + 3], w3, h[j]);
            }
        }
        for (; k < 143; ++k) {
            const float w0 = wt[k * 256];
#pragma unroll
            for (int j = 0; j < CTX_J; ++j) h[j] = fmaf(s_ca[j][k], w0, h[j]);
        }

        // ---- batched block LayerNorm over 256 dims ----
#pragma unroll
        for (int j = 0; j < CTX_J; ++j) {
            float a = h[j], b = h[j] * h[j];
#pragma unroll
            for (int o = 16; o; o >>= 1) {
                a += __shfl_xor_sync(0xffffffffu, a, o);
                b += __shfl_xor_sync(0xffffffffu, b, o);
            }
            if (lane == 0) { s_red[wid][j][0] = a; s_red[wid][j][1] = b; }
        }
        __syncthreads();
        if (tid < CTX_J) {
            float t1 = 0.f, t2 = 0.f;
#pragma unroll
            for (int w = 0; w < 8; ++w) { t1 += s_red[w][tid][0]; t2 += s_red[w][tid][1]; }
            const float mu  = t1 * (1.f / 256.f);
            const float var = t2 * (1.f / 256.f) - mu * mu;
            s_ms[tid][0] = mu;
            s_ms[tid][1] = rsqrtf(var + 1e-5f);
        }
        __syncthreads();

        // ---- epilogue: relu(LN) added onto already-stored embedding ----
        for (int j = 0; j < J; ++j) {
            const int tt = s_clist[base + j];
            const float v = fmaf((h[j] - s_ms[j][0]) * s_ms[j][1], cg, ce);
            out[(size_t)tt * 256 + tid] += fmaxf(v, 0.f);
        }
        __syncthreads();   // s_ca/s_red reuse guard
    }
}

} // namespace

extern "C" void kernel_launch(void* const* d_in, const int* in_sizes, int n_in,
                              void* d_out, int out_size)
{
    const int tokens = in_sizes[0];   // N*S

    poker_fused_kernel<<<NB_MAIN, 256>>>(
        (const int*)  d_in[0],   // token_ids
        (const int*)  d_in[1],   // token_streets
        (const int*)  d_in[2],   // card_ranks
        (const int*)  d_in[3],   // card_suits
        (const int*)  d_in[4],   // action_actors
        (const float*)d_in[5],   // action_legal_masks
        (const float*)d_in[6],   // context_features
        (const float*)d_in[7],   // base_emb
        (const float*)d_in[8],   // street_emb
        (const float*)d_in[9],   // rank_emb
        (const float*)d_in[10],  // suit_emb
        (const float*)d_in[11],  // actor_emb
        (const float*)d_in[12],  // atype_emb
        (const float*)d_in[13],  // legal_W
        (const float*)d_in[14],  // legal_b
        (const float*)d_in[15],  // legal_g
        (const float*)d_in[16],  // legal_beta
        (const float*)d_in[17],  // game_W
        (const float*)d_in[18],  // game_b
        (const float*)d_in[19],  // game_g
        (const float*)d_in[20],  // game_beta
        (const float*)d_in[21],  // ctx_W
        (const float*)d_in[22],  // ctx_b
        (const float*)d_in[23],  // ctx_g
        (const float*)d_in[24],  // ctx_beta
        (float*)d_out,
        tokens);
}